// round 10
// baseline (speedup 1.0000x reference)
#include <cuda_runtime.h>
#include <cuda_fp16.h>
#include <math.h>
#include <stdint.h>

#define NB    4
#define HWSZ  4096
#define KDIM  2304
#define NCH   (KDIM / 32)      // 72 k-chunks of 32

// ---------------------------------------------------------------------------
// Scratch (device globals)
// ---------------------------------------------------------------------------
__device__ float g_t1[NB * 256 * HWSZ];                 // fp32 activations
__device__ float g_t2[NB * 256 * HWSZ];
__device__ float g_t3[NB * 432 * HWSZ];
__device__ __half g_cols[(size_t)NB * KDIM * HWSZ];     // deform sampled B (fp16)
__device__ __half g_wh[1280 * KDIM];                    // packed weights fp16

#define DST_T1  0
#define DST_T2  1
#define DST_T3  2
#define DST_OUT 3

// B source selector
#define BSRC_EXT  0
#define BSRC_T1   1
#define BSRC_T2   2
#define BSRC_COLS 3

// ---------------------------------------------------------------------------
// PTX helpers (family-common, valid on target sm_100)
// ---------------------------------------------------------------------------
static __device__ __forceinline__ uint32_t smem_u32(const void* p) {
    uint32_t a;
    asm("{ .reg .u64 t; cvta.to.shared.u64 t, %1; cvt.u32.u64 %0, t; }" : "=r"(a) : "l"(p));
    return a;
}
#define CP16(dst, src) \
    asm volatile("cp.async.cg.shared.global [%0], [%1], 16;" :: "r"(dst), "l"(src))
#define CP_COMMIT()  asm volatile("cp.async.commit_group;" ::: "memory")
#define CP_WAIT2()   asm volatile("cp.async.wait_group 2;" ::: "memory")
#define CP_WAIT1()   asm volatile("cp.async.wait_group 1;" ::: "memory")
#define CP_WAIT0()   asm volatile("cp.async.wait_group 0;" ::: "memory")

#define LDSM_X4(r, addr) \
    asm volatile("ldmatrix.sync.aligned.m8n8.x4.shared.b16 {%0,%1,%2,%3}, [%4];" \
        : "=r"((r)[0]), "=r"((r)[1]), "=r"((r)[2]), "=r"((r)[3]) : "r"(addr))
#define LDSM_X2T(r, addr) \
    asm volatile("ldmatrix.sync.aligned.m8n8.x2.trans.shared.b16 {%0,%1}, [%2];" \
        : "=r"((r)[0]), "=r"((r)[1]) : "r"(addr))

#define MMA_F16(d, a, b) \
    asm volatile("mma.sync.aligned.m16n8k16.row.col.f32.f16.f16.f32 " \
        "{%0,%1,%2,%3}, {%4,%5,%6,%7}, {%8,%9}, {%0,%1,%2,%3};" \
        : "+f"((d)[0]), "+f"((d)[1]), "+f"((d)[2]), "+f"((d)[3]) \
        : "r"((a)[0]), "r"((a)[1]), "r"((a)[2]), "r"((a)[3]), "r"((b)[0]), "r"((b)[1]))

// ---------------------------------------------------------------------------
// Weight pre-convert: pack w1|w2|w3(padded to 512)|weight into fp16
// (1280 rows x 2304).
// ---------------------------------------------------------------------------
__global__ void convw_k(const float* __restrict__ w1, const float* __restrict__ w2,
                        const float* __restrict__ w3, const float* __restrict__ wm)
{
    int idx = blockIdx.x * 256 + threadIdx.x;
    int row = idx / KDIM;
    int col = idx - row * KDIM;
    float v = 0.f;
    if (row < 256)       v = w1[row * KDIM + col];
    else if (row < 512)  v = w2[(row - 256) * KDIM + col];
    else if (row < 1024) { int r = row - 512; if (r < 432) v = w3[r * KDIM + col]; }
    else                 v = wm[(row - 1024) * KDIM + col];
    g_wh[idx] = __float2half_rn(v);
}

// ---------------------------------------------------------------------------
// Deformable bilinear sampling -> fp16 plane (deform stage only)
// ---------------------------------------------------------------------------
__global__ void sample_k(const float* __restrict__ x)
{
    const int b  = blockIdx.z;
    const int gk = blockIdx.y;
    const int g  = gk / 9;
    const int k  = gk - g * 9;
    const int ki = k / 3;
    const int kj = k - ki * 3;
    const int p  = blockIdx.x * 256 + threadIdx.x;
    const int y  = p >> 6;
    const int xx = p & 63;

    const float* t3b = g_t3 + (size_t)b * 432 * HWSZ;
    const float dy = t3b[(g * 18 + 2 * k) * HWSZ + p];
    const float dx = t3b[(g * 18 + 2 * k + 1) * HWSZ + p];
    float mv       = t3b[(288 + g * 9 + k) * HWSZ + p];
    mv = 1.f / (1.f + expf(-mv));

    const float ys  = (float)(y - 1 + ki) + dy;
    const float xs  = (float)(xx - 1 + kj) + dx;
    const float y0f = floorf(ys);
    const float x0f = floorf(xs);
    const float wy  = ys - y0f;
    const float wx  = xs - x0f;
    const int y0 = (int)y0f;
    const int x0 = (int)x0f;

    const bool vy0 = ((unsigned)y0       < 64u);
    const bool vy1 = ((unsigned)(y0 + 1) < 64u);
    const bool vx0 = ((unsigned)x0       < 64u);
    const bool vx1 = ((unsigned)(x0 + 1) < 64u);

    float w00 = (vy0 && vx0) ? (1.f - wy) * (1.f - wx) * mv : 0.f;
    float w01 = (vy0 && vx1) ? (1.f - wy) * wx         * mv : 0.f;
    float w10 = (vy1 && vx0) ? wy * (1.f - wx)         * mv : 0.f;
    float w11 = (vy1 && vx1) ? wy * wx                 * mv : 0.f;

    const int yc0 = min(max(y0, 0), 63);
    const int yc1 = min(max(y0 + 1, 0), 63);
    const int xc0 = min(max(x0, 0), 63);
    const int xc1 = min(max(x0 + 1, 0), 63);
    const int i00 = (yc0 << 6) + xc0;
    const int i01 = (yc0 << 6) + xc1;
    const int i10 = (yc1 << 6) + xc0;
    const int i11 = (yc1 << 6) + xc1;

    const float* xb = x + ((size_t)b * 256 + g * 16) * HWSZ;
    const size_t base = ((size_t)b * KDIM + (g * 16) * 9 + k) * HWSZ + p;

#pragma unroll
    for (int c = 0; c < 16; ++c) {
        const float* xc = xb + c * HWSZ;
        float v = w00 * xc[i00] + w01 * xc[i01] + w10 * xc[i10] + w11 * xc[i11];
        g_cols[base + (size_t)c * 9 * HWSZ] = __float2half_rn(v);
    }
}

// ---------------------------------------------------------------------------
// HMMA fp16 GEMM with FUSED im2col B-loader.
// CTA tile (NI*64)m x 64n x 32k, 3-stage pipeline.
//   C[b][moff+m][n] = sum_k W[aoff+m][k] * B[b][k][n] + bias[moff+m] (+SiLU)
// B built on the fly from fp32 activations (3x3 im2col view; n-tile = one
// image row) or streamed from g_cols (deform). 8 warps = 4m x 2n,
// warp tile (NI*16)x32, mma m16n8k16 fp16.
// SMEM: A [stage][256m][80B], B [stage][32k][144B]
// ---------------------------------------------------------------------------
#define A_ST   20480     // 256*80
#define B_OFF  61440     // 3 A stages
#define B_ST   4608      // 32*144
#define SMEM_TOT (B_OFF + 3 * B_ST)   // 75264

template<int NI>
__global__ void __launch_bounds__(256)
gemm_tc(int aoff, int moff, const float* __restrict__ bias, float* __restrict__ extC,
        int M, int act, int dstsel, int bsrc, const float* __restrict__ extB)
{
    extern __shared__ char smem[];
    const uint32_t sb = smem_u32(smem);
    const int tid  = threadIdx.x;
    const int lane = tid & 31;
    const int wid  = tid >> 5;
    const int wm   = wid >> 1;          // 0..3  (m)
    const int wn   = wid & 1;           // 0..1  (n)
    const int yimg = blockIdx.y;        // image row = n-tile
    const int n0   = yimg * 64;
    const int b    = blockIdx.z;

    float* C = (dstsel == DST_T1) ? g_t1
             : (dstsel == DST_T2) ? g_t2
             : (dstsel == DST_T3) ? g_t3 : extC;
    float* Cb = C + (size_t)b * M * HWSZ;

    const __half* gA = g_wh + (size_t)aoff * KDIM;
    const bool useCols = (bsrc == BSRC_COLS);
    const float* srcf = (bsrc == BSRC_T1) ? g_t1
                      : (bsrc == BSRC_T2) ? g_t2 : extB;
    const __half* gB = g_cols + (size_t)b * KDIM * HWSZ;

    // B mappings
    const int kk   = tid >> 3;                  // direct: k-row 0..31
    const int xseg = (tid & 7) * 8;             // direct: 8-px segment
    const int bkr  = tid >> 3, bnc = tid & 7;   // cols path: same shape

    auto issueA = [&](int t, int st) {
        const int k0 = t * 32;
#pragma unroll
        for (int it = 0; it < 4; ++it) {        // A: 1024 ld16 over 256 threads
            int idx = tid + it * 256;
            int row = idx >> 2, kc = idx & 3;
            uint32_t dst = sb + st * A_ST + row * 80 + kc * 16;
            CP16(dst, gA + (size_t)row * KDIM + k0 + kc * 8);
        }
        if (useCols) {
            uint32_t dstB = sb + B_OFF + st * B_ST + bkr * 144 + bnc * 16;
            CP16(dstB, gB + (size_t)(k0 + bkr) * HWSZ + n0 + bnc * 8);
        }
        CP_COMMIT();
    };

    // Direct im2col B build: thread's 8 fp16 values for k-row kk, x in
    // [xseg, xseg+8). B[k][y*64+x] = src[cin][y+ki-1][x+kj-1] (0 outside).
    // NOTE: all window values live in named registers (no misaligned vector
    // casts into local arrays, no dynamic indexing -> no local-mem spill).
    auto loadB = [&](int t, uint32_t o[4]) {
        if (useCols) return;
        const int kg  = t * 32 + kk;
        const int cin = kg / 9;
        const int tap = kg - cin * 9;
        const int ki  = tap / 3;
        const int kj  = tap - ki * 3;
        const int ys  = yimg + ki - 1;
        float v[10];
        if ((unsigned)ys < 64u) {
            const float* row = srcf + ((size_t)(b * 256 + cin) << 12) + (ys << 6);
            const float4 pa = *(const float4*)(row + xseg);
            const float4 pb = *(const float4*)(row + xseg + 4);
            v[0] = (xseg > 0)  ? row[xseg - 1] : 0.f;
            v[1] = pa.x; v[2] = pa.y; v[3] = pa.z; v[4] = pa.w;
            v[5] = pb.x; v[6] = pb.y; v[7] = pb.z; v[8] = pb.w;
            v[9] = (xseg < 56) ? row[xseg + 8] : 0.f;
        } else {
#pragma unroll
            for (int e = 0; e < 10; ++e) v[e] = 0.f;
        }
        // branchless kj-shift: static indices only (register-resident)
        __half h[8];
#pragma unroll
        for (int e = 0; e < 8; ++e) {
            float val = (kj == 0) ? v[e] : (kj == 1) ? v[e + 1] : v[e + 2];
            h[e] = __float2half_rn(val);
        }
        uint4 u = *(uint4*)h;
        o[0] = u.x; o[1] = u.y; o[2] = u.z; o[3] = u.w;
    };
    auto stsB = [&](int st, const uint32_t o[4]) {
        if (useCols) return;
        *(uint4*)(smem + B_OFF + st * B_ST + kk * 144 + xseg * 2) =
            make_uint4(o[0], o[1], o[2], o[3]);
    };

    float acc[NI][4][4];
#pragma unroll
    for (int i = 0; i < NI; ++i)
#pragma unroll
        for (int j = 0; j < 4; ++j)
#pragma unroll
            for (int q = 0; q < 4; ++q) acc[i][j][q] = 0.f;

    uint32_t bo[4];
    issueA(0, 0); loadB(0, bo); stsB(0, bo);
    issueA(1, 1); loadB(1, bo); stsB(1, bo);

    for (int t = 0; t < NCH; ++t) {
        const int st = t % 3;
        const bool pre = (t + 2 < NCH);
        if (pre) { issueA(t + 2, (t + 2) % 3); loadB(t + 2, bo); }
        if (pre)               { CP_WAIT2(); }
        else if (t + 1 < NCH)  { CP_WAIT1(); }
        else                   { CP_WAIT0(); }
        __syncthreads();

        const uint32_t aB = sb + st * A_ST;
        const uint32_t bB = sb + B_OFF + st * B_ST;
#pragma unroll
        for (int s = 0; s < 2; ++s) {
            uint32_t bf[4][2];
            const uint32_t brow = (uint32_t)(s * 16 + (lane & 15));
#pragma unroll
            for (int j = 0; j < 4; ++j)
                LDSM_X2T(bf[j], bB + brow * 144 + (uint32_t)(wn * 32 + j * 8) * 2);

            const uint32_t arow = (uint32_t)(wm * (16 * NI) + (lane & 15));
            const uint32_t acol = (uint32_t)(s * 32 + (lane >> 4) * 16);
            uint32_t ah[NI][4];
#pragma unroll
            for (int i = 0; i < NI; ++i)
                LDSM_X4(ah[i], aB + (arow + i * 16) * 80 + acol);
#pragma unroll
            for (int i = 0; i < NI; ++i)
#pragma unroll
                for (int j = 0; j < 4; ++j)
                    MMA_F16(acc[i][j], ah[i], bf[j]);
        }
        if (pre) stsB((t + 2) % 3, bo);
        __syncthreads();
    }

    // epilogue: bias (+SiLU), float2 stores
#pragma unroll
    for (int i = 0; i < NI; ++i) {
        const int r0 = moff + wm * (16 * NI) + i * 16 + (lane >> 2);
#pragma unroll
        for (int h = 0; h < 2; ++h) {
            const int r = r0 + h * 8;
            if (r < M) {
                const float bv = bias[r];
                float* dst = Cb + (size_t)r * HWSZ + n0 + wn * 32 + (lane & 3) * 2;
#pragma unroll
                for (int j = 0; j < 4; ++j) {
                    float v0 = acc[i][j][h * 2 + 0] + bv;
                    float v1 = acc[i][j][h * 2 + 1] + bv;
                    if (act) {
                        v0 = v0 / (1.f + expf(-v0));
                        v1 = v1 / (1.f + expf(-v1));
                    }
                    *(float2*)(dst + j * 8) = make_float2(v0, v1);
                }
            }
        }
    }
}

// ---------------------------------------------------------------------------
// Launch sequence:
//   convw -> conv1(fused im2col) -> conv2(fused) -> conv3(fused, 256+192 rows)
//   -> sample -> deform GEMM (B from g_cols)
// ---------------------------------------------------------------------------
extern "C" void kernel_launch(void* const* d_in, const int* in_sizes, int n_in,
                              void* d_out, int out_size)
{
    (void)in_sizes; (void)n_in; (void)out_size;
    const float* x      = (const float*)d_in[0];
    const float* offf   = (const float*)d_in[1];
    const float* weight = (const float*)d_in[2];
    const float* bias   = (const float*)d_in[3];
    const float* w1     = (const float*)d_in[4];
    const float* b1     = (const float*)d_in[5];
    const float* w2     = (const float*)d_in[6];
    const float* b2     = (const float*)d_in[7];
    const float* w3     = (const float*)d_in[8];
    const float* b3     = (const float*)d_in[9];
    float* out = (float*)d_out;

    cudaFuncSetAttribute(gemm_tc<4>, cudaFuncAttributeMaxDynamicSharedMemorySize, SMEM_TOT);
    cudaFuncSetAttribute(gemm_tc<3>, cudaFuncAttributeMaxDynamicSharedMemorySize, SMEM_TOT);

    dim3 gg(1, 64, NB);

    convw_k<<<(1280 * KDIM) / 256, 256>>>(w1, w2, w3, weight);

    gemm_tc<4><<<gg, 256, SMEM_TOT>>>(0,    0,   b1,   nullptr, 256, 1, DST_T1, BSRC_EXT, offf);
    gemm_tc<4><<<gg, 256, SMEM_TOT>>>(256,  0,   b2,   nullptr, 256, 1, DST_T2, BSRC_T1,  nullptr);
    gemm_tc<4><<<gg, 256, SMEM_TOT>>>(512,  0,   b3,   nullptr, 432, 0, DST_T3, BSRC_T2,  nullptr);
    gemm_tc<3><<<gg, 256, SMEM_TOT>>>(768,  256, b3,   nullptr, 432, 0, DST_T3, BSRC_T2,  nullptr);

    sample_k<<<dim3(16, 144, NB), 256>>>(x);
    gemm_tc<4><<<gg, 256, SMEM_TOT>>>(1024, 0,   bias, out,     256, 0, DST_OUT, BSRC_COLS, nullptr);
}

// round 11
// speedup vs baseline: 1.2221x; 1.2221x over previous
#include <cuda_runtime.h>
#include <cuda_fp16.h>
#include <math.h>
#include <stdint.h>

#define NB    4
#define HWSZ  4096
#define KDIM  2304
#define NCH   (KDIM / 32)      // 72 k-chunks of 32

// ---------------------------------------------------------------------------
// Scratch (device globals)
// ---------------------------------------------------------------------------
__device__ __half g_t1h[NB * 256 * HWSZ];               // fp16 activations
__device__ __half g_t2h[NB * 256 * HWSZ];
__device__ float  g_t3[NB * 432 * HWSZ];                // conv3 out (fp32)
__device__ __half g_cols[(size_t)NB * KDIM * HWSZ];     // B fp16 plane (75.5MB)
__device__ __half g_wh[1280 * KDIM];                    // packed weights fp16

#define DST_T1H 0
#define DST_T2H 1
#define DST_T3  2
#define DST_OUT 3

// ---------------------------------------------------------------------------
// PTX helpers (family-common, valid on target sm_100)
// ---------------------------------------------------------------------------
static __device__ __forceinline__ uint32_t smem_u32(const void* p) {
    uint32_t a;
    asm("{ .reg .u64 t; cvta.to.shared.u64 t, %1; cvt.u32.u64 %0, t; }" : "=r"(a) : "l"(p));
    return a;
}
#define CP16(dst, src) \
    asm volatile("cp.async.cg.shared.global [%0], [%1], 16;" :: "r"(dst), "l"(src))
#define CP_COMMIT()  asm volatile("cp.async.commit_group;" ::: "memory")
#define CP_WAIT2()   asm volatile("cp.async.wait_group 2;" ::: "memory")
#define CP_WAIT1()   asm volatile("cp.async.wait_group 1;" ::: "memory")
#define CP_WAIT0()   asm volatile("cp.async.wait_group 0;" ::: "memory")

#define LDSM_X4(r, addr) \
    asm volatile("ldmatrix.sync.aligned.m8n8.x4.shared.b16 {%0,%1,%2,%3}, [%4];" \
        : "=r"((r)[0]), "=r"((r)[1]), "=r"((r)[2]), "=r"((r)[3]) : "r"(addr))
#define LDSM_X2T(r, addr) \
    asm volatile("ldmatrix.sync.aligned.m8n8.x2.trans.shared.b16 {%0,%1}, [%2];" \
        : "=r"((r)[0]), "=r"((r)[1]) : "r"(addr))

#define MMA_F16(d, a, b) \
    asm volatile("mma.sync.aligned.m16n8k16.row.col.f32.f16.f16.f32 " \
        "{%0,%1,%2,%3}, {%4,%5,%6,%7}, {%8,%9}, {%0,%1,%2,%3};" \
        : "+f"((d)[0]), "+f"((d)[1]), "+f"((d)[2]), "+f"((d)[3]) \
        : "r"((a)[0]), "r"((a)[1]), "r"((a)[2]), "r"((a)[3]), "r"((b)[0]), "r"((b)[1]))

static __device__ __forceinline__ uint32_t h2u(__half2 h) {
    return *(uint32_t*)&h;
}

// ---------------------------------------------------------------------------
// Weight pre-convert: pack w1|w2|w3(padded to 512)|weight into fp16
// (1280 rows x 2304).
// ---------------------------------------------------------------------------
__global__ void convw_k(const float* __restrict__ w1, const float* __restrict__ w2,
                        const float* __restrict__ w3, const float* __restrict__ wm)
{
    int idx = blockIdx.x * 256 + threadIdx.x;
    int row = idx / KDIM;
    int col = idx - row * KDIM;
    float v = 0.f;
    if (row < 256)       v = w1[row * KDIM + col];
    else if (row < 512)  v = w2[(row - 256) * KDIM + col];
    else if (row < 1024) { int r = row - 512; if (r < 432) v = w3[r * KDIM + col]; }
    else                 v = wm[(row - 1024) * KDIM + col];
    g_wh[idx] = __float2half_rn(v);
}

// ---------------------------------------------------------------------------
// im2col (fp32 source) -> fp16 plane. One thread: one (b,cin,ki,y) row segment
// of 8 outputs for ALL 3 kj taps. (Unchanged from the measured 15.7us kernel.)
// ---------------------------------------------------------------------------
__global__ void im2col_f(const float* __restrict__ src)
{
    int idx  = blockIdx.x * 256 + threadIdx.x;  // NB*256*3*64*8 threads
    int xc   = idx & 7;
    int x0   = xc * 8;
    int y    = (idx >> 3) & 63;
    int rest = idx >> 9;
    int ki   = rest % 3;
    int t2   = rest / 3;
    int cin  = t2 & 255;
    int b    = t2 >> 8;
    int ys   = y + ki - 1;

    float v[10];
    if ((unsigned)ys < 64u) {
        const float* row = src + ((size_t)(b * 256 + cin) << 12) + (ys << 6);
        const float4 pa = *(const float4*)(row + x0);
        const float4 pb = *(const float4*)(row + x0 + 4);
        v[0] = (x0 > 0)  ? row[x0 - 1] : 0.f;
        v[1] = pa.x; v[2] = pa.y; v[3] = pa.z; v[4] = pa.w;
        v[5] = pb.x; v[6] = pb.y; v[7] = pb.z; v[8] = pb.w;
        v[9] = (x0 < 56) ? row[x0 + 8] : 0.f;
    } else {
#pragma unroll
        for (int e = 0; e < 10; ++e) v[e] = 0.f;
    }

    __half h[10];
#pragma unroll
    for (int e = 0; e < 10; ++e) h[e] = __float2half_rn(v[e]);

    const size_t obase = ((size_t)(b * KDIM + cin * 9 + ki * 3) << 12) + (y << 6) + x0;
#pragma unroll
    for (int kj = 0; kj < 3; ++kj) {
        __half o[8];
#pragma unroll
        for (int e = 0; e < 8; ++e) o[e] = h[kj + e];
        *(uint4*)&g_cols[obase + ((size_t)kj << 12)] = *(uint4*)o;
    }
}

// ---------------------------------------------------------------------------
// im2col (fp16 source) -> fp16 plane. Register-resident uint4/half2 shuffles
// only (no vector casts into local arrays — the round-9 misalignment lesson).
// ---------------------------------------------------------------------------
__global__ void im2col_h(int srcsel)   // 1 = g_t1h, 2 = g_t2h
{
    const __half* src = (srcsel == 1) ? g_t1h : g_t2h;
    int idx  = blockIdx.x * 256 + threadIdx.x;
    int xc   = idx & 7;
    int x0   = xc * 8;
    int y    = (idx >> 3) & 63;
    int rest = idx >> 9;
    int ki   = rest % 3;
    int t2   = rest / 3;
    int cin  = t2 & 255;
    int b    = t2 >> 8;
    int ys   = y + ki - 1;

    uint4 u = make_uint4(0u, 0u, 0u, 0u);
    __half l = __ushort_as_half(0), r = __ushort_as_half(0);
    if ((unsigned)ys < 64u) {
        const __half* row = src + ((size_t)(b * 256 + cin) << 12) + (ys << 6);
        u = *(const uint4*)(row + x0);          // a0..a7 (16B aligned)
        if (x0 > 0)  l = row[x0 - 1];
        if (x0 < 56) r = row[x0 + 8];
    }
    const __half2 p0 = *(__half2*)&u.x;         // (a0,a1)
    const __half2 p1 = *(__half2*)&u.y;         // (a2,a3)
    const __half2 p2 = *(__half2*)&u.z;         // (a4,a5)
    const __half2 p3 = *(__half2*)&u.w;         // (a6,a7)

    // kj=0 window {l,a0..a6}; kj=1 window {a0..a7}=u; kj=2 window {a1..a7,r}
    const __half2 w0a = __halves2half2(l, __low2half(p0));
    const __half2 mid1 = __halves2half2(__high2half(p0), __low2half(p1));
    const __half2 mid2 = __halves2half2(__high2half(p1), __low2half(p2));
    const __half2 mid3 = __halves2half2(__high2half(p2), __low2half(p3));
    const __half2 w2d = __halves2half2(__high2half(p3), r);

    const size_t obase = ((size_t)(b * KDIM + cin * 9 + ki * 3) << 12) + (y << 6) + x0;
    *(uint4*)&g_cols[obase]        = make_uint4(h2u(w0a), h2u(mid1), h2u(mid2), h2u(mid3));
    *(uint4*)&g_cols[obase + 4096] = u;
    *(uint4*)&g_cols[obase + 8192] = make_uint4(h2u(mid1), h2u(mid2), h2u(mid3), h2u(w2d));
}

// ---------------------------------------------------------------------------
// Deformable bilinear sampling -> fp16 plane
// ---------------------------------------------------------------------------
__global__ void sample_k(const float* __restrict__ x)
{
    const int b  = blockIdx.z;
    const int gk = blockIdx.y;
    const int g  = gk / 9;
    const int k  = gk - g * 9;
    const int ki = k / 3;
    const int kj = k - ki * 3;
    const int p  = blockIdx.x * 256 + threadIdx.x;
    const int y  = p >> 6;
    const int xx = p & 63;

    const float* t3b = g_t3 + (size_t)b * 432 * HWSZ;
    const float dy = t3b[(g * 18 + 2 * k) * HWSZ + p];
    const float dx = t3b[(g * 18 + 2 * k + 1) * HWSZ + p];
    float mv       = t3b[(288 + g * 9 + k) * HWSZ + p];
    mv = 1.f / (1.f + expf(-mv));

    const float ys  = (float)(y - 1 + ki) + dy;
    const float xs  = (float)(xx - 1 + kj) + dx;
    const float y0f = floorf(ys);
    const float x0f = floorf(xs);
    const float wy  = ys - y0f;
    const float wx  = xs - x0f;
    const int y0 = (int)y0f;
    const int x0 = (int)x0f;

    const bool vy0 = ((unsigned)y0       < 64u);
    const bool vy1 = ((unsigned)(y0 + 1) < 64u);
    const bool vx0 = ((unsigned)x0       < 64u);
    const bool vx1 = ((unsigned)(x0 + 1) < 64u);

    float w00 = (vy0 && vx0) ? (1.f - wy) * (1.f - wx) * mv : 0.f;
    float w01 = (vy0 && vx1) ? (1.f - wy) * wx         * mv : 0.f;
    float w10 = (vy1 && vx0) ? wy * (1.f - wx)         * mv : 0.f;
    float w11 = (vy1 && vx1) ? wy * wx                 * mv : 0.f;

    const int yc0 = min(max(y0, 0), 63);
    const int yc1 = min(max(y0 + 1, 0), 63);
    const int xc0 = min(max(x0, 0), 63);
    const int xc1 = min(max(x0 + 1, 0), 63);
    const int i00 = (yc0 << 6) + xc0;
    const int i01 = (yc0 << 6) + xc1;
    const int i10 = (yc1 << 6) + xc0;
    const int i11 = (yc1 << 6) + xc1;

    const float* xb = x + ((size_t)b * 256 + g * 16) * HWSZ;
    const size_t base = ((size_t)b * KDIM + (g * 16) * 9 + k) * HWSZ + p;

#pragma unroll
    for (int c = 0; c < 16; ++c) {
        const float* xc = xb + c * HWSZ;
        float v = w00 * xc[i00] + w01 * xc[i01] + w10 * xc[i10] + w11 * xc[i11];
        g_cols[base + (size_t)c * 9 * HWSZ] = __float2half_rn(v);
    }
}

// ---------------------------------------------------------------------------
// HMMA fp16 GEMM, CTA tile (NI*64)m x 64n x 32k, 3-stage cp.async pipeline.
//   C[b][moff+m][n] = sum_k W[aoff+m][k] * g_cols[b][k][n] + bias[moff+m] (+SiLU)
// 8 warps = 4m x 2n, warp tile (NI*16)x32, mma m16n8k16 fp16.
// SMEM: A [stage][256m][80B], B [stage][32k][144B]
// ---------------------------------------------------------------------------
#define A_ST   20480     // 256*80
#define B_OFF  61440     // 3 A stages
#define B_ST   4608      // 32*144
#define SMEM_TOT (B_OFF + 3 * B_ST)   // 75264

template<int NI>
__global__ void __launch_bounds__(256)
gemm_tc(int aoff, int moff, const float* __restrict__ bias, float* __restrict__ extC,
        int M, int act, int dstsel)
{
    extern __shared__ char smem[];
    const uint32_t sb = smem_u32(smem);
    const int tid  = threadIdx.x;
    const int lane = tid & 31;
    const int wid  = tid >> 5;
    const int wm   = wid >> 1;          // 0..3  (m)
    const int wn   = wid & 1;           // 0..1  (n)
    const int n0   = blockIdx.y * 64;
    const int b    = blockIdx.z;

    const bool h16 = (dstsel == DST_T1H) || (dstsel == DST_T2H);
    float*  Cf = ((dstsel == DST_T3) ? g_t3 : extC) + (size_t)b * M * HWSZ;
    __half* Ch = ((dstsel == DST_T1H) ? g_t1h : g_t2h) + (size_t)b * 256 * HWSZ;

    const __half* gA = g_wh + (size_t)aoff * KDIM;
    const __half* gB = g_cols + (size_t)b * KDIM * HWSZ;

    const int bkr = tid >> 3, bnc = tid & 7;   // B: 32 k-rows x 8 chunks

    auto issue = [&](int t, int st) {
        const int k0 = t * 32;
#pragma unroll
        for (int it = 0; it < 4; ++it) {        // A: 1024 ld16 over 256 threads
            int idx = tid + it * 256;
            int row = idx >> 2, kc = idx & 3;
            uint32_t dst = sb + st * A_ST + row * 80 + kc * 16;
            CP16(dst, gA + (size_t)row * KDIM + k0 + kc * 8);
        }
        uint32_t dstB = sb + B_OFF + st * B_ST + bkr * 144 + bnc * 16;
        CP16(dstB, gB + (size_t)(k0 + bkr) * HWSZ + n0 + bnc * 8);
        CP_COMMIT();
    };

    float acc[NI][4][4];
#pragma unroll
    for (int i = 0; i < NI; ++i)
#pragma unroll
        for (int j = 0; j < 4; ++j)
#pragma unroll
            for (int q = 0; q < 4; ++q) acc[i][j][q] = 0.f;

    issue(0, 0);
    issue(1, 1);

    for (int t = 0; t < NCH; ++t) {
        const int st = t % 3;
        if (t + 2 < NCH) { issue(t + 2, (t + 2) % 3); CP_WAIT2(); }
        else if (t + 1 < NCH) { CP_WAIT1(); }
        else { CP_WAIT0(); }
        __syncthreads();

        const uint32_t aB = sb + st * A_ST;
        const uint32_t bB = sb + B_OFF + st * B_ST;
#pragma unroll
        for (int s = 0; s < 2; ++s) {
            uint32_t bf[4][2];
            const uint32_t brow = (uint32_t)(s * 16 + (lane & 15));
#pragma unroll
            for (int j = 0; j < 4; ++j)
                LDSM_X2T(bf[j], bB + brow * 144 + (uint32_t)(wn * 32 + j * 8) * 2);

            const uint32_t arow = (uint32_t)(wm * (16 * NI) + (lane & 15));
            const uint32_t acol = (uint32_t)(s * 32 + (lane >> 4) * 16);
            uint32_t ah[NI][4];
#pragma unroll
            for (int i = 0; i < NI; ++i)
                LDSM_X4(ah[i], aB + (arow + i * 16) * 80 + acol);
#pragma unroll
            for (int i = 0; i < NI; ++i)
#pragma unroll
                for (int j = 0; j < 4; ++j)
                    MMA_F16(acc[i][j], ah[i], bf[j]);
        }
        __syncthreads();
    }

    // epilogue: bias (+SiLU); fp32 or fp16 destination
#pragma unroll
    for (int i = 0; i < NI; ++i) {
        const int r0 = moff + wm * (16 * NI) + i * 16 + (lane >> 2);
#pragma unroll
        for (int h = 0; h < 2; ++h) {
            const int r = r0 + h * 8;
            if (r < M) {
                const float bv = bias[r];
                const size_t off = (size_t)r * HWSZ + n0 + wn * 32 + (lane & 3) * 2;
#pragma unroll
                for (int j = 0; j < 4; ++j) {
                    float v0 = acc[i][j][h * 2 + 0] + bv;
                    float v1 = acc[i][j][h * 2 + 1] + bv;
                    if (act) {
                        v0 = v0 / (1.f + expf(-v0));
                        v1 = v1 / (1.f + expf(-v1));
                    }
                    if (h16) {
                        *(__half2*)(Ch + off + j * 8) = __floats2half2_rn(v0, v1);
                    } else {
                        *(float2*)(Cf + off + j * 8) = make_float2(v0, v1);
                    }
                }
            }
        }
    }
}

// ---------------------------------------------------------------------------
// Launch sequence
// ---------------------------------------------------------------------------
extern "C" void kernel_launch(void* const* d_in, const int* in_sizes, int n_in,
                              void* d_out, int out_size)
{
    (void)in_sizes; (void)n_in; (void)out_size;
    const float* x      = (const float*)d_in[0];
    const float* offf   = (const float*)d_in[1];
    const float* weight = (const float*)d_in[2];
    const float* bias   = (const float*)d_in[3];
    const float* w1     = (const float*)d_in[4];
    const float* b1     = (const float*)d_in[5];
    const float* w2     = (const float*)d_in[6];
    const float* b2     = (const float*)d_in[7];
    const float* w3     = (const float*)d_in[8];
    const float* b3     = (const float*)d_in[9];
    float* out = (float*)d_out;

    cudaFuncSetAttribute(gemm_tc<4>, cudaFuncAttributeMaxDynamicSharedMemorySize, SMEM_TOT);
    cudaFuncSetAttribute(gemm_tc<3>, cudaFuncAttributeMaxDynamicSharedMemorySize, SMEM_TOT);

    const int IMB = (NB * 256 * 3 * 64 * 8) / 256;   // 6144 blocks
    dim3 gg(1, 64, NB);

    convw_k<<<(1280 * KDIM) / 256, 256>>>(w1, w2, w3, weight);

    im2col_f<<<IMB, 256>>>(offf);
    gemm_tc<4><<<gg, 256, SMEM_TOT>>>(0,    0,   b1,   nullptr, 256, 1, DST_T1H);

    im2col_h<<<IMB, 256>>>(1);
    gemm_tc<4><<<gg, 256, SMEM_TOT>>>(256,  0,   b2,   nullptr, 256, 1, DST_T2H);

    im2col_h<<<IMB, 256>>>(2);
    gemm_tc<4><<<gg, 256, SMEM_TOT>>>(512,  0,   b3,   nullptr, 432, 0, DST_T3);
    gemm_tc<3><<<gg, 256, SMEM_TOT>>>(768,  256, b3,   nullptr, 432, 0, DST_T3);

    sample_k<<<dim3(16, 144, NB), 256>>>(x);
    gemm_tc<4><<<gg, 256, SMEM_TOT>>>(1024, 0,   bias, out,     256, 0, DST_OUT);
}

// round 12
// speedup vs baseline: 1.3404x; 1.0967x over previous
#include <cuda_runtime.h>
#include <cuda_fp16.h>
#include <math.h>
#include <stdint.h>

#define NB    4
#define HWSZ  4096
#define KDIM  2304
#define NST   (KDIM / 64)      // 36 k-stages of 64

// ---------------------------------------------------------------------------
// Scratch (device globals)
// ---------------------------------------------------------------------------
__device__ __half g_t1h[NB * 256 * HWSZ];               // fp16 activations
__device__ __half g_t2h[NB * 256 * HWSZ];
__device__ float  g_t3[NB * 432 * HWSZ];                // conv3 out (fp32)
__device__ __half g_cols[(size_t)NB * KDIM * HWSZ];     // B fp16 plane (75.5MB)
__device__ __half g_wh[1280 * KDIM];                    // packed weights fp16

#define DST_T1H 0
#define DST_T2H 1
#define DST_T3  2
#define DST_OUT 3

// ---------------------------------------------------------------------------
// PTX helpers (family-common, valid on target sm_100)
// ---------------------------------------------------------------------------
static __device__ __forceinline__ uint32_t smem_u32(const void* p) {
    uint32_t a;
    asm("{ .reg .u64 t; cvta.to.shared.u64 t, %1; cvt.u32.u64 %0, t; }" : "=r"(a) : "l"(p));
    return a;
}
#define CP16(dst, src) \
    asm volatile("cp.async.cg.shared.global [%0], [%1], 16;" :: "r"(dst), "l"(src))
#define CP_COMMIT()  asm volatile("cp.async.commit_group;" ::: "memory")
#define CP_WAIT1()   asm volatile("cp.async.wait_group 1;" ::: "memory")
#define CP_WAIT0()   asm volatile("cp.async.wait_group 0;" ::: "memory")

#define LDSM_X4(r, addr) \
    asm volatile("ldmatrix.sync.aligned.m8n8.x4.shared.b16 {%0,%1,%2,%3}, [%4];" \
        : "=r"((r)[0]), "=r"((r)[1]), "=r"((r)[2]), "=r"((r)[3]) : "r"(addr))
#define LDSM_X2T(r, addr) \
    asm volatile("ldmatrix.sync.aligned.m8n8.x2.trans.shared.b16 {%0,%1}, [%2];" \
        : "=r"((r)[0]), "=r"((r)[1]) : "r"(addr))

#define MMA_F16(d, a, b) \
    asm volatile("mma.sync.aligned.m16n8k16.row.col.f32.f16.f16.f32 " \
        "{%0,%1,%2,%3}, {%4,%5,%6,%7}, {%8,%9}, {%0,%1,%2,%3};" \
        : "+f"((d)[0]), "+f"((d)[1]), "+f"((d)[2]), "+f"((d)[3]) \
        : "r"((a)[0]), "r"((a)[1]), "r"((a)[2]), "r"((a)[3]), "r"((b)[0]), "r"((b)[1]))

static __device__ __forceinline__ uint32_t h2u(__half2 h) {
    return *(uint32_t*)&h;
}

// ---------------------------------------------------------------------------
// Weight pre-convert: pack w1|w2|w3(padded to 512)|weight into fp16
// ---------------------------------------------------------------------------
__global__ void convw_k(const float* __restrict__ w1, const float* __restrict__ w2,
                        const float* __restrict__ w3, const float* __restrict__ wm)
{
    int idx = blockIdx.x * 256 + threadIdx.x;
    int row = idx / KDIM;
    int col = idx - row * KDIM;
    float v = 0.f;
    if (row < 256)       v = w1[row * KDIM + col];
    else if (row < 512)  v = w2[(row - 256) * KDIM + col];
    else if (row < 1024) { int r = row - 512; if (r < 432) v = w3[r * KDIM + col]; }
    else                 v = wm[(row - 1024) * KDIM + col];
    g_wh[idx] = __float2half_rn(v);
}

// ---------------------------------------------------------------------------
// im2col (fp32 source) -> fp16 plane.
// ---------------------------------------------------------------------------
__global__ void im2col_f(const float* __restrict__ src)
{
    int idx  = blockIdx.x * 256 + threadIdx.x;
    int xc   = idx & 7;
    int x0   = xc * 8;
    int y    = (idx >> 3) & 63;
    int rest = idx >> 9;
    int ki   = rest % 3;
    int t2   = rest / 3;
    int cin  = t2 & 255;
    int b    = t2 >> 8;
    int ys   = y + ki - 1;

    float v[10];
    if ((unsigned)ys < 64u) {
        const float* row = src + ((size_t)(b * 256 + cin) << 12) + (ys << 6);
        const float4 pa = *(const float4*)(row + x0);
        const float4 pb = *(const float4*)(row + x0 + 4);
        v[0] = (x0 > 0)  ? row[x0 - 1] : 0.f;
        v[1] = pa.x; v[2] = pa.y; v[3] = pa.z; v[4] = pa.w;
        v[5] = pb.x; v[6] = pb.y; v[7] = pb.z; v[8] = pb.w;
        v[9] = (x0 < 56) ? row[x0 + 8] : 0.f;
    } else {
#pragma unroll
        for (int e = 0; e < 10; ++e) v[e] = 0.f;
    }

    __half h[10];
#pragma unroll
    for (int e = 0; e < 10; ++e) h[e] = __float2half_rn(v[e]);

    const size_t obase = ((size_t)(b * KDIM + cin * 9 + ki * 3) << 12) + (y << 6) + x0;
#pragma unroll
    for (int kj = 0; kj < 3; ++kj) {
        __half o[8];
#pragma unroll
        for (int e = 0; e < 8; ++e) o[e] = h[kj + e];
        *(uint4*)&g_cols[obase + ((size_t)kj << 12)] = *(uint4*)o;
    }
}

// ---------------------------------------------------------------------------
// im2col (fp16 source) -> fp16 plane. Register-resident shuffles only.
// ---------------------------------------------------------------------------
__global__ void im2col_h(int srcsel)   // 1 = g_t1h, 2 = g_t2h
{
    const __half* src = (srcsel == 1) ? g_t1h : g_t2h;
    int idx  = blockIdx.x * 256 + threadIdx.x;
    int xc   = idx & 7;
    int x0   = xc * 8;
    int y    = (idx >> 3) & 63;
    int rest = idx >> 9;
    int ki   = rest % 3;
    int t2   = rest / 3;
    int cin  = t2 & 255;
    int b    = t2 >> 8;
    int ys   = y + ki - 1;

    uint4 u = make_uint4(0u, 0u, 0u, 0u);
    __half l = __ushort_as_half(0), r = __ushort_as_half(0);
    if ((unsigned)ys < 64u) {
        const __half* row = src + ((size_t)(b * 256 + cin) << 12) + (ys << 6);
        u = *(const uint4*)(row + x0);
        if (x0 > 0)  l = row[x0 - 1];
        if (x0 < 56) r = row[x0 + 8];
    }
    const __half2 p0 = *(__half2*)&u.x;
    const __half2 p1 = *(__half2*)&u.y;
    const __half2 p2 = *(__half2*)&u.z;
    const __half2 p3 = *(__half2*)&u.w;

    const __half2 w0a  = __halves2half2(l, __low2half(p0));
    const __half2 mid1 = __halves2half2(__high2half(p0), __low2half(p1));
    const __half2 mid2 = __halves2half2(__high2half(p1), __low2half(p2));
    const __half2 mid3 = __halves2half2(__high2half(p2), __low2half(p3));
    const __half2 w2d  = __halves2half2(__high2half(p3), r);

    const size_t obase = ((size_t)(b * KDIM + cin * 9 + ki * 3) << 12) + (y << 6) + x0;
    *(uint4*)&g_cols[obase]        = make_uint4(h2u(w0a), h2u(mid1), h2u(mid2), h2u(mid3));
    *(uint4*)&g_cols[obase + 4096] = u;
    *(uint4*)&g_cols[obase + 8192] = make_uint4(h2u(mid1), h2u(mid2), h2u(mid3), h2u(w2d));
}

// ---------------------------------------------------------------------------
// Deformable bilinear sampling -> fp16 plane
// ---------------------------------------------------------------------------
__global__ void sample_k(const float* __restrict__ x)
{
    const int b  = blockIdx.z;
    const int gk = blockIdx.y;
    const int g  = gk / 9;
    const int k  = gk - g * 9;
    const int ki = k / 3;
    const int kj = k - ki * 3;
    const int p  = blockIdx.x * 256 + threadIdx.x;
    const int y  = p >> 6;
    const int xx = p & 63;

    const float* t3b = g_t3 + (size_t)b * 432 * HWSZ;
    const float dy = t3b[(g * 18 + 2 * k) * HWSZ + p];
    const float dx = t3b[(g * 18 + 2 * k + 1) * HWSZ + p];
    float mv       = t3b[(288 + g * 9 + k) * HWSZ + p];
    mv = 1.f / (1.f + expf(-mv));

    const float ys  = (float)(y - 1 + ki) + dy;
    const float xs  = (float)(xx - 1 + kj) + dx;
    const float y0f = floorf(ys);
    const float x0f = floorf(xs);
    const float wy  = ys - y0f;
    const float wx  = xs - x0f;
    const int y0 = (int)y0f;
    const int x0 = (int)x0f;

    const bool vy0 = ((unsigned)y0       < 64u);
    const bool vy1 = ((unsigned)(y0 + 1) < 64u);
    const bool vx0 = ((unsigned)x0       < 64u);
    const bool vx1 = ((unsigned)(x0 + 1) < 64u);

    float w00 = (vy0 && vx0) ? (1.f - wy) * (1.f - wx) * mv : 0.f;
    float w01 = (vy0 && vx1) ? (1.f - wy) * wx         * mv : 0.f;
    float w10 = (vy1 && vx0) ? wy * (1.f - wx)         * mv : 0.f;
    float w11 = (vy1 && vx1) ? wy * wx                 * mv : 0.f;

    const int yc0 = min(max(y0, 0), 63);
    const int yc1 = min(max(y0 + 1, 0), 63);
    const int xc0 = min(max(x0, 0), 63);
    const int xc1 = min(max(x0 + 1, 0), 63);
    const int i00 = (yc0 << 6) + xc0;
    const int i01 = (yc0 << 6) + xc1;
    const int i10 = (yc1 << 6) + xc0;
    const int i11 = (yc1 << 6) + xc1;

    const float* xb = x + ((size_t)b * 256 + g * 16) * HWSZ;
    const size_t base = ((size_t)b * KDIM + (g * 16) * 9 + k) * HWSZ + p;

#pragma unroll
    for (int c = 0; c < 16; ++c) {
        const float* xc = xb + c * HWSZ;
        float v = w00 * xc[i00] + w01 * xc[i01] + w10 * xc[i10] + w11 * xc[i11];
        g_cols[base + (size_t)c * 9 * HWSZ] = __float2half_rn(v);
    }
}

// ---------------------------------------------------------------------------
// HMMA fp16 GEMM, CTA tile (NI*64)m x 64n x 64k, 2-stage cp.async pipeline.
//   C[b][moff+m][n] = sum_k W[aoff+m][k] * g_cols[b][k][n] + bias[moff+m] (+SiLU)
// 8 warps = 4m x 2n, warp tile (NI*16)x32, mma m16n8k16 fp16.
// SMEM stage: A [256m][144B] + B [64k][144B] = 46080 B; 2 stages = 92160 B.
// ---------------------------------------------------------------------------
#define STG    46080     // one stage
#define A_B    36864     // 256*144 (B tile starts after A within a stage)
#define SMEM_TOT (2 * STG)   // 92160

template<int NI>
__global__ void __launch_bounds__(256)
gemm_tc(int aoff, int moff, const float* __restrict__ bias, float* __restrict__ extC,
        int M, int act, int dstsel)
{
    extern __shared__ char smem[];
    const uint32_t sb = smem_u32(smem);
    const int tid  = threadIdx.x;
    const int lane = tid & 31;
    const int wid  = tid >> 5;
    const int wm   = wid >> 1;          // 0..3  (m)
    const int wn   = wid & 1;           // 0..1  (n)
    const int n0   = blockIdx.y * 64;
    const int b    = blockIdx.z;

    const bool h16 = (dstsel == DST_T1H) || (dstsel == DST_T2H);
    float*  Cf = ((dstsel == DST_T3) ? g_t3 : extC) + (size_t)b * M * HWSZ;
    __half* Ch = ((dstsel == DST_T1H) ? g_t1h : g_t2h) + (size_t)b * 256 * HWSZ;

    const __half* gA = g_wh + (size_t)aoff * KDIM;
    const __half* gB = g_cols + (size_t)b * KDIM * HWSZ;

    auto issue = [&](int t, int st) {
        const int k0 = t * 64;
        const uint32_t base = sb + st * STG;
#pragma unroll
        for (int it = 0; it < 8; ++it) {        // A: 2048 ld16 over 256 threads
            int idx = tid + it * 256;
            int row = idx >> 3, kc = idx & 7;
            CP16(base + row * 144 + kc * 16,
                 gA + (size_t)row * KDIM + k0 + kc * 8);
        }
#pragma unroll
        for (int it = 0; it < 2; ++it) {        // B: 512 ld16
            int idx = tid + it * 256;
            int row = idx >> 3, nc = idx & 7;
            CP16(base + A_B + row * 144 + nc * 16,
                 gB + (size_t)(k0 + row) * HWSZ + n0 + nc * 8);
        }
        CP_COMMIT();
    };

    float acc[NI][4][4];
#pragma unroll
    for (int i = 0; i < NI; ++i)
#pragma unroll
        for (int j = 0; j < 4; ++j)
#pragma unroll
            for (int q = 0; q < 4; ++q) acc[i][j][q] = 0.f;

    issue(0, 0);

    for (int t = 0; t < NST; ++t) {
        const int st = t & 1;
        if (t + 1 < NST) { issue(t + 1, st ^ 1); CP_WAIT1(); }
        else             { CP_WAIT0(); }
        __syncthreads();

        const uint32_t aB = sb + st * STG;
        const uint32_t bB = aB + A_B;
#pragma unroll
        for (int s = 0; s < 4; ++s) {
            uint32_t bf[4][2];
            const uint32_t brow = (uint32_t)(s * 16 + (lane & 15));
#pragma unroll
            for (int j = 0; j < 4; ++j)
                LDSM_X2T(bf[j], bB + brow * 144 + (uint32_t)(wn * 32 + j * 8) * 2);

            const uint32_t arow = (uint32_t)(wm * (16 * NI) + (lane & 15));
            const uint32_t acol = (uint32_t)(s * 32 + (lane >> 4) * 16);
            uint32_t ah[NI][4];
#pragma unroll
            for (int i = 0; i < NI; ++i)
                LDSM_X4(ah[i], aB + (arow + i * 16) * 144 + acol);
#pragma unroll
            for (int i = 0; i < NI; ++i)
#pragma unroll
                for (int j = 0; j < 4; ++j)
                    MMA_F16(acc[i][j], ah[i], bf[j]);
        }
        __syncthreads();
    }

    // epilogue: bias (+SiLU); fp32 or fp16 destination
#pragma unroll
    for (int i = 0; i < NI; ++i) {
        const int r0 = moff + wm * (16 * NI) + i * 16 + (lane >> 2);
#pragma unroll
        for (int h = 0; h < 2; ++h) {
            const int r = r0 + h * 8;
            if (r < M) {
                const float bv = bias[r];
                const size_t off = (size_t)r * HWSZ + n0 + wn * 32 + (lane & 3) * 2;
#pragma unroll
                for (int j = 0; j < 4; ++j) {
                    float v0 = acc[i][j][h * 2 + 0] + bv;
                    float v1 = acc[i][j][h * 2 + 1] + bv;
                    if (act) {
                        v0 = v0 / (1.f + expf(-v0));
                        v1 = v1 / (1.f + expf(-v1));
                    }
                    if (h16) {
                        *(__half2*)(Ch + off + j * 8) = __floats2half2_rn(v0, v1);
                    } else {
                        *(float2*)(Cf + off + j * 8) = make_float2(v0, v1);
                    }
                }
            }
        }
    }
}

// ---------------------------------------------------------------------------
// Launch sequence
// ---------------------------------------------------------------------------
extern "C" void kernel_launch(void* const* d_in, const int* in_sizes, int n_in,
                              void* d_out, int out_size)
{
    (void)in_sizes; (void)n_in; (void)out_size;
    const float* x      = (const float*)d_in[0];
    const float* offf   = (const float*)d_in[1];
    const float* weight = (const float*)d_in[2];
    const float* bias   = (const float*)d_in[3];
    const float* w1     = (const float*)d_in[4];
    const float* b1     = (const float*)d_in[5];
    const float* w2     = (const float*)d_in[6];
    const float* b2     = (const float*)d_in[7];
    const float* w3     = (const float*)d_in[8];
    const float* b3     = (const float*)d_in[9];
    float* out = (float*)d_out;

    cudaFuncSetAttribute(gemm_tc<4>, cudaFuncAttributeMaxDynamicSharedMemorySize, SMEM_TOT);
    cudaFuncSetAttribute(gemm_tc<3>, cudaFuncAttributeMaxDynamicSharedMemorySize, SMEM_TOT);

    const int IMB = (NB * 256 * 3 * 64 * 8) / 256;   // 6144 blocks
    dim3 gg(1, 64, NB);

    convw_k<<<(1280 * KDIM) / 256, 256>>>(w1, w2, w3, weight);

    im2col_f<<<IMB, 256>>>(offf);
    gemm_tc<4><<<gg, 256, SMEM_TOT>>>(0,    0,   b1,   nullptr, 256, 1, DST_T1H);

    im2col_h<<<IMB, 256>>>(1);
    gemm_tc<4><<<gg, 256, SMEM_TOT>>>(256,  0,   b2,   nullptr, 256, 1, DST_T2H);

    im2col_h<<<IMB, 256>>>(2);
    gemm_tc<4><<<gg, 256, SMEM_TOT>>>(512,  0,   b3,   nullptr, 432, 0, DST_T3);
    gemm_tc<3><<<gg, 256, SMEM_TOT>>>(768,  256, b3,   nullptr, 432, 0, DST_T3);

    sample_k<<<dim3(16, 144, NB), 256>>>(x);
    gemm_tc<4><<<gg, 256, SMEM_TOT>>>(1024, 0,   bias, out,     256, 0, DST_OUT);
}